// round 10
// baseline (speedup 1.0000x reference)
#include <cuda_runtime.h>
#include <cstdint>

typedef unsigned long long ull;

#define SEQ    96
#define NHEAD  8
#define DHEAD  32
#define DMOD   256
#define NBATCH 1024
#define MTOT   (NBATCH*SEQ)   // 98304

// ---------------- scratch (static device globals) ----------------
__device__ float g_q[NBATCH*NHEAD*SEQ*DHEAD];
__device__ float g_k[NBATCH*NHEAD*SEQ*DHEAD];
__device__ float g_v[NBATCH*NHEAD*SEQ*DHEAD];
__device__ float g_ao[MTOT*DMOD];

// ---------------- helpers ----------------
__device__ __forceinline__ ull pack2(float x, float y) {
    ull r; asm("mov.b64 %0, {%1,%2};" : "=l"(r) : "f"(x), "f"(y)); return r;
}
__device__ __forceinline__ void ffma2(ull &d, ull a, ull b) {
    asm("fma.rn.f32x2 %0, %1, %2, %0;" : "+l"(d) : "l"(a), "l"(b));
}
__device__ __forceinline__ float2 unpack2(ull v) {
    float2 f; asm("mov.b64 {%0,%1}, %2;" : "=f"(f.x), "=f"(f.y) : "l"(v)); return f;
}
__device__ __forceinline__ uint32_t smem_u32(const void* p){
    uint32_t a;
    asm("{ .reg .u64 t; cvta.to.shared.u64 t, %1; cvt.u32.u64 %0, t; }" : "=r"(a) : "l"(p));
    return a;
}
__device__ __forceinline__ void ldsm4(uint32_t& r0, uint32_t& r1, uint32_t& r2,
                                      uint32_t& r3, uint32_t a){
    asm volatile("ldmatrix.sync.aligned.m8n8.x4.shared.b16 {%0,%1,%2,%3}, [%4];"
        : "=r"(r0), "=r"(r1), "=r"(r2), "=r"(r3) : "r"(a));
}
__device__ __forceinline__ void mma_bf16(float* c, const uint32_t* a,
                                         uint32_t b0, uint32_t b1){
    asm volatile("mma.sync.aligned.m16n8k16.row.col.f32.bf16.bf16.f32 "
        "{%0,%1,%2,%3}, {%4,%5,%6,%7}, {%8,%9}, {%0,%1,%2,%3};"
        : "+f"(c[0]), "+f"(c[1]), "+f"(c[2]), "+f"(c[3])
        : "r"(a[0]), "r"(a[1]), "r"(a[2]), "r"(a[3]), "r"(b0), "r"(b1));
}
__device__ __forceinline__ void bsplit2(float x, float y, uint32_t& h2, uint32_t& l2){
    asm("cvt.rn.bf16x2.f32 %0, %1, %2;" : "=r"(h2) : "f"(y), "f"(x));
    float hx = __uint_as_float(h2 << 16);
    float hy = __uint_as_float(h2 & 0xffff0000u);
    float rx = x - hx;
    float ry = y - hy;
    asm("cvt.rn.bf16x2.f32 %0, %1, %2;" : "=r"(l2) : "f"(ry), "f"(rx));
}
__device__ __forceinline__ void sts128(uint32_t a, uint32_t r0, uint32_t r1,
                                       uint32_t r2, uint32_t r3){
    asm volatile("st.shared.v4.b32 [%0], {%1,%2,%3,%4};"
        :: "r"(a), "r"(r0), "r"(r1), "r"(r2), "r"(r3) : "memory");
}

// SMEM stage layout (bf16 tiles, rows padded to 80B)
#define ROWB  80
#define ST_AH 0
#define ST_AL 10240
#define ST_BH 20480
#define ST_BL 40960
#define STG   61440
#define SMEMB (2*STG)   // 122880

// ---------------- bf16x3 tensor-core GEMM (R9-proven, term-reordered) -------
template<int QKV>
__global__ void __launch_bounds__(256, 1) gemm_mma(
    const float* __restrict__ Ain,
    const float* __restrict__ W0, const float* __restrict__ W1,
    const float* __restrict__ W2,
    float* __restrict__ Cout)
{
    extern __shared__ __align__(128) char smem[];
    const uint32_t sb = smem_u32(smem);
    const int tid  = threadIdx.x;
    const int lane = tid & 31;
    const int wid  = tid >> 5;

    const float* W; float* dst;
    if (QKV) {
        const int z = blockIdx.y;
        W   = (z == 0) ? W0  : (z == 1) ? W1  : W2;
        dst = (z == 0) ? g_q : (z == 1) ? g_k : g_v;
    } else { W = W0; dst = Cout; }
    const float* Ab = QKV ? Ain : (const float*)g_ao;
    const int m0 = blockIdx.x * 128;

    const int ar = tid & 127;
    const int ah = (tid >> 7) << 4;
    const float* gA = Ab + (size_t)(m0 + ar) * DMOD + ah;
    const uint32_t aDst = (uint32_t)ar * ROWB + (uint32_t)(ah << 1);
    const float* gB = W + tid;
    const uint32_t bDst = (uint32_t)tid * ROWB;

    const int mW = (wid & 1) * 64;
    const int nW = (wid >> 1) * 64;
    const int q  = lane >> 3;
    const int rl = lane & 7;
    const uint32_t aOff = (uint32_t)(mW + (q & 1) * 8 + rl) * ROWB + (uint32_t)((q >> 1) * 16);
    const uint32_t bOff = (uint32_t)(nW + (q >> 1) * 8 + rl) * ROWB + (uint32_t)((q & 1) * 16);

    float acc[4][8][4];
    #pragma unroll
    for (int mi = 0; mi < 4; mi++)
        #pragma unroll
        for (int ni = 0; ni < 8; ni++)
            #pragma unroll
            for (int t = 0; t < 4; t++) acc[mi][ni][t] = 0.f;

    float fa[16], fb[32];

    auto ldgA = [&](int c){
        const float* p = gA + c * 32;
        *(float4*)(fa + 0)  = *(const float4*)(p + 0);
        *(float4*)(fa + 4)  = *(const float4*)(p + 4);
        *(float4*)(fa + 8)  = *(const float4*)(p + 8);
        *(float4*)(fa + 12) = *(const float4*)(p + 12);
    };
    auto ldgB = [&](int c){
        const float* p = gB + (size_t)c * 32 * DMOD;
        #pragma unroll
        for (int i = 0; i < 32; i++) fb[i] = p[(size_t)i * DMOD];
    };
    auto stsAB = [&](uint32_t sBase){
        uint32_t h[16], l[16];
        #pragma unroll
        for (int i = 0; i < 8; i++) bsplit2(fa[2*i], fa[2*i+1], h[i], l[i]);
        sts128(sBase + ST_AH + aDst,      h[0], h[1], h[2], h[3]);
        sts128(sBase + ST_AH + aDst + 16, h[4], h[5], h[6], h[7]);
        sts128(sBase + ST_AL + aDst,      l[0], l[1], l[2], l[3]);
        sts128(sBase + ST_AL + aDst + 16, l[4], l[5], l[6], l[7]);
        #pragma unroll
        for (int i = 0; i < 16; i++) bsplit2(fb[2*i], fb[2*i+1], h[i], l[i]);
        sts128(sBase + ST_BH + bDst,      h[0],  h[1],  h[2],  h[3]);
        sts128(sBase + ST_BH + bDst + 16, h[4],  h[5],  h[6],  h[7]);
        sts128(sBase + ST_BH + bDst + 32, h[8],  h[9],  h[10], h[11]);
        sts128(sBase + ST_BH + bDst + 48, h[12], h[13], h[14], h[15]);
        sts128(sBase + ST_BL + bDst,      l[0],  l[1],  l[2],  l[3]);
        sts128(sBase + ST_BL + bDst + 16, l[4],  l[5],  l[6],  l[7]);
        sts128(sBase + ST_BL + bDst + 32, l[8],  l[9],  l[10], l[11]);
        sts128(sBase + ST_BL + bDst + 48, l[12], l[13], l[14], l[15]);
    };

    ldgA(0); ldgB(0);
    stsAB(sb);
    ldgA(1); ldgB(1);
    __syncthreads();

    #pragma unroll 1
    for (int c = 0; c < 8; c++){
        const uint32_t sBuf = sb + (uint32_t)(c & 1) * STG;
        const uint32_t aH = sBuf + ST_AH + aOff;
        const uint32_t aL = sBuf + ST_AL + aOff;
        const uint32_t bH = sBuf + ST_BH + bOff;
        const uint32_t bL = sBuf + ST_BL + bOff;
        #pragma unroll
        for (int k16 = 0; k16 < 2; k16++){
            const uint32_t ko = (uint32_t)k16 * 32;
            uint32_t A_[16], A2_[16], B_[16];
            #pragma unroll
            for (int mi = 0; mi < 4; mi++)
                ldsm4(A_[4*mi], A_[4*mi+1], A_[4*mi+2], A_[4*mi+3],
                      aH + ko + (uint32_t)mi * (16*ROWB));
            #pragma unroll
            for (int mi = 0; mi < 4; mi++)
                ldsm4(A2_[4*mi], A2_[4*mi+1], A2_[4*mi+2], A2_[4*mi+3],
                      aL + ko + (uint32_t)mi * (16*ROWB));
            #pragma unroll
            for (int j = 0; j < 4; j++)
                ldsm4(B_[4*j], B_[4*j+1], B_[4*j+2], B_[4*j+3],
                      bH + ko + (uint32_t)j * (16*ROWB));
            #pragma unroll
            for (int mi = 0; mi < 4; mi++)
                #pragma unroll
                for (int ni = 0; ni < 8; ni++)
                    mma_bf16(acc[mi][ni], &A_[4*mi], B_[2*ni], B_[2*ni+1]);
            #pragma unroll
            for (int mi = 0; mi < 4; mi++)
                #pragma unroll
                for (int ni = 0; ni < 8; ni++)
                    mma_bf16(acc[mi][ni], &A2_[4*mi], B_[2*ni], B_[2*ni+1]);
            #pragma unroll
            for (int j = 0; j < 4; j++)
                ldsm4(B_[4*j], B_[4*j+1], B_[4*j+2], B_[4*j+3],
                      bL + ko + (uint32_t)j * (16*ROWB));
            #pragma unroll
            for (int mi = 0; mi < 4; mi++)
                #pragma unroll
                for (int ni = 0; ni < 8; ni++)
                    mma_bf16(acc[mi][ni], &A_[4*mi], B_[2*ni], B_[2*ni+1]);
        }
        if (c < 7) stsAB(sb + (uint32_t)((c + 1) & 1) * STG);
        if (c < 6) { ldgA(c + 2); ldgB(c + 2); }
        __syncthreads();
    }

    const int r0q = lane >> 2;
    const int c0q = (lane & 3) * 2;
    #pragma unroll
    for (int mi = 0; mi < 4; mi++){
        #pragma unroll
        for (int half = 0; half < 2; half++){
            const int row = m0 + mW + mi * 16 + half * 8 + r0q;
            if (QKV){
                const int nb = row / SEQ, l = row % SEQ;
                float* base = dst + (((size_t)nb * NHEAD) * SEQ + l) * DHEAD;
                #pragma unroll
                for (int ni = 0; ni < 8; ni++){
                    const int col = nW + ni * 8 + c0q;
                    const int h = col >> 5, cc = col & 31;
                    float2 v;
                    v.x = acc[mi][ni][half*2+0];
                    v.y = acc[mi][ni][half*2+1];
                    *(float2*)(base + (size_t)h * (SEQ*DHEAD) + cc) = v;
                }
            } else {
                float* base = dst + (size_t)row * DMOD;
                #pragma unroll
                for (int ni = 0; ni < 8; ni++){
                    const int col = nW + ni * 8 + c0q;
                    float2 v;
                    v.x = acc[mi][ni][half*2+0];
                    v.y = acc[mi][ni][half*2+1];
                    *(float2*)(base + col) = v;
                }
            }
        }
    }
}

// ---------------- attention: fused single-pass, 2 queries/thread -----------
// Max-free softmax (logits ~N(0,1); exp safe in fp32). No logit storage.
// Swizzle p(j) = 17j + (j>>1) (R6-verified conflict-free).
#define ATT_SW(j)   ((uint32_t)(j)*17u + ((uint32_t)(j)>>1))
#define GRP_ULL     1678u                 // p(95)+16
#define BIAS_F      (4u*GRP_ULL*2u)       // float index 13424
#define ATT_BYTES   ((BIAS_F + 66u)*4u)   // 53960

__global__ void __launch_bounds__(96, 6) attn2q(const float* __restrict__ rel_bias)
{
    extern __shared__ __align__(16) ull smp[];
    float* fs = (float*)smp;
    const int tid = threadIdx.x;
    const int g = tid / 48;
    const int t = tid - g * 48;
    const int nh0 = blockIdx.x * 2;

    // fill K/V swizzled: pools (ull): k0 @0, k1 @GRP, v0 @2GRP, v1 @3GRP
    for (int idx = tid; idx < 6144; idx += 96){
        const int gg = idx / 3072;
        const int e  = idx - gg * 3072;
        const int r = e >> 5, c = e & 31;
        const uint32_t w = 2u * ATT_SW(r) + (uint32_t)c;
        fs[(uint32_t)gg * (2u*GRP_ULL) + w]       = g_k[(size_t)(nh0 + gg) * 3072 + e];
        fs[(uint32_t)(2 + gg) * (2u*GRP_ULL) + w] = g_v[(size_t)(nh0 + gg) * 3072 + e];
    }
    if (tid < 66){
        const int gg = tid / 33, d = tid - gg * 33;
        const int h = (nh0 + gg) & 7;
        const int rel = (112 - d) % 96;     // (i-j) mod 96 for offset d-16
        fs[BIAS_F + gg * 33 + d] = rel_bias[h * 96 + rel];
    }
    __syncthreads();

    const int nh = nh0 + g;
    const int q0 = 2 * t;
    const float* sbias = fs + BIAS_F + g * 33;
    const ull* kpool = smp + (size_t)g * GRP_ULL;
    const ull* vpool = smp + (size_t)(2 + g) * GRP_ULL;

    ull qq0[16], qq1[16];
    {
        const float* qg = g_q + (size_t)nh * 3072 + (size_t)q0 * 32;
        #pragma unroll
        for (int u = 0; u < 16; u++){
            float2 a = *(const float2*)(qg + 2*u);
            float2 b = *(const float2*)(qg + 32 + 2*u);
            qq0[u] = pack2(a.x, a.y);
            qq1[u] = pack2(b.x, b.y);
        }
    }

    const float scale = 0.17677669529663687f;   // 1/sqrt(32)
    ull o0[16], o1[16];
    #pragma unroll
    for (int u = 0; u < 16; u++){ o0[u] = 0ull; o1[u] = 0ull; }
    float s0 = 0.f, s1 = 0.f;

    #pragma unroll
    for (int d = 0; d < 34; d++){
        int j = q0 - 16 + d;
        if (j < 0)   j += 96;
        if (j >= 96) j -= 96;
        const uint32_t sw = ATT_SW(j);

        // QK: shared K row serves both queries
        const ull* kp = kpool + sw;
        ull a0 = 0ull, a1 = 0ull;
        #pragma unroll
        for (int u = 0; u < 16; u++){
            ull kv = kp[u];
            if (d < 33) ffma2(a0, qq0[u], kv);
            if (d > 0)  ffma2(a1, qq1[u], kv);
        }
        float w0 = 0.f, w1 = 0.f;
        if (d < 33){
            float2 s2 = unpack2(a0);
            w0 = __expf((s2.x + s2.y) * scale + sbias[d]);
            s0 += w0;
        }
        if (d > 0){
            float2 s2 = unpack2(a1);
            w1 = __expf((s2.x + s2.y) * scale + sbias[d-1]);
            s1 += w1;
        }

        // PV: shared V row serves both queries
        const ull* vp = vpool + sw;
        const ull ww0 = pack2(w0, w0);
        const ull ww1 = pack2(w1, w1);
        #pragma unroll
        for (int u = 0; u < 16; u++){
            ull vv = vp[u];
            if (d < 33) ffma2(o0[u], ww0, vv);
            if (d > 0)  ffma2(o1[u], ww1, vv);
        }
    }

    const float inv0 = 1.0f / s0, inv1 = 1.0f / s1;
    float* og = g_ao + ((size_t)(nh >> 3) * SEQ + q0) * DMOD + (size_t)(nh & 7) * DHEAD;
    #pragma unroll
    for (int u = 0; u < 16; u++){
        float2 v0 = unpack2(o0[u]);
        float2 r0v; r0v.x = v0.x * inv0; r0v.y = v0.y * inv0;
        *(float2*)(og + 2*u) = r0v;
        float2 v1 = unpack2(o1[u]);
        float2 r1v; r1v.x = v1.x * inv1; r1v.y = v1.y * inv1;
        *(float2*)(og + DMOD + 2*u) = r1v;
    }
}

// ---------------- entry point ----------------
extern "C" void kernel_launch(void* const* d_in, const int* in_sizes, int n_in,
                              void* d_out, int out_size)
{
    (void)in_sizes; (void)n_in; (void)out_size;
    const float* Z  = (const float*)d_in[0];
    const float* Wq = (const float*)d_in[1];
    const float* Wk = (const float*)d_in[2];
    const float* Wv = (const float*)d_in[3];
    const float* Wo = (const float*)d_in[4];
    const float* rb = (const float*)d_in[5];
    float* out = (float*)d_out;

    cudaFuncSetAttribute(gemm_mma<1>, cudaFuncAttributeMaxDynamicSharedMemorySize, SMEMB);
    cudaFuncSetAttribute(gemm_mma<0>, cudaFuncAttributeMaxDynamicSharedMemorySize, SMEMB);
    cudaFuncSetAttribute(attn2q,      cudaFuncAttributeMaxDynamicSharedMemorySize, ATT_BYTES);

    dim3 g1(MTOT / 128, 3);
    gemm_mma<1><<<g1, 256, SMEMB>>>(Z, Wq, Wk, Wv, nullptr);

    attn2q<<<NBATCH * NHEAD / 2, 96, ATT_BYTES>>>(rb);

    dim3 g2(MTOT / 128, 1);
    gemm_mma<0><<<g2, 256, SMEMB>>>(nullptr, Wo, nullptr, nullptr, out);
}

// round 11
// speedup vs baseline: 1.4185x; 1.4185x over previous
#include <cuda_runtime.h>
#include <cstdint>

typedef unsigned long long ull;

#define SEQ    96
#define NHEAD  8
#define DHEAD  32
#define DMOD   256
#define NBATCH 1024
#define MTOT   (NBATCH*SEQ)   // 98304
#define NDIAG  33

// ---------------- scratch (static device globals) ----------------
__device__ float g_q[NBATCH*NHEAD*SEQ*DHEAD];
__device__ float g_k[NBATCH*NHEAD*SEQ*DHEAD];
__device__ float g_v[NBATCH*NHEAD*SEQ*DHEAD];
__device__ float g_ao[MTOT*DMOD];

// ---------------- helpers ----------------
__device__ __forceinline__ ull pack2(float x, float y) {
    ull r; asm("mov.b64 %0, {%1,%2};" : "=l"(r) : "f"(x), "f"(y)); return r;
}
__device__ __forceinline__ void ffma2(ull &d, ull a, ull b) {
    asm("fma.rn.f32x2 %0, %1, %2, %0;" : "+l"(d) : "l"(a), "l"(b));
}
__device__ __forceinline__ float2 unpack2(ull v) {
    float2 f; asm("mov.b64 {%0,%1}, %2;" : "=f"(f.x), "=f"(f.y) : "l"(v)); return f;
}
__device__ __forceinline__ uint32_t smem_u32(const void* p){
    uint32_t a;
    asm("{ .reg .u64 t; cvta.to.shared.u64 t, %1; cvt.u32.u64 %0, t; }" : "=r"(a) : "l"(p));
    return a;
}
__device__ __forceinline__ void ldsm4(uint32_t& r0, uint32_t& r1, uint32_t& r2,
                                      uint32_t& r3, uint32_t a){
    asm volatile("ldmatrix.sync.aligned.m8n8.x4.shared.b16 {%0,%1,%2,%3}, [%4];"
        : "=r"(r0), "=r"(r1), "=r"(r2), "=r"(r3) : "r"(a));
}
__device__ __forceinline__ void mma_bf16(float* c, const uint32_t* a,
                                         uint32_t b0, uint32_t b1){
    asm volatile("mma.sync.aligned.m16n8k16.row.col.f32.bf16.bf16.f32 "
        "{%0,%1,%2,%3}, {%4,%5,%6,%7}, {%8,%9}, {%0,%1,%2,%3};"
        : "+f"(c[0]), "+f"(c[1]), "+f"(c[2]), "+f"(c[3])
        : "r"(a[0]), "r"(a[1]), "r"(a[2]), "r"(a[3]), "r"(b0), "r"(b1));
}
__device__ __forceinline__ void bsplit2(float x, float y, uint32_t& h2, uint32_t& l2){
    asm("cvt.rn.bf16x2.f32 %0, %1, %2;" : "=r"(h2) : "f"(y), "f"(x));
    float hx = __uint_as_float(h2 << 16);
    float hy = __uint_as_float(h2 & 0xffff0000u);
    float rx = x - hx;
    float ry = y - hy;
    asm("cvt.rn.bf16x2.f32 %0, %1, %2;" : "=r"(l2) : "f"(ry), "f"(rx));
}
__device__ __forceinline__ void sts128(uint32_t a, uint32_t r0, uint32_t r1,
                                       uint32_t r2, uint32_t r3){
    asm volatile("st.shared.v4.b32 [%0], {%1,%2,%3,%4};"
        :: "r"(a), "r"(r0), "r"(r1), "r"(r2), "r"(r3) : "memory");
}

// SMEM stage layout (bf16 tiles, rows padded to 80B)
#define ROWB  80
#define ST_AH 0
#define ST_AL 10240
#define ST_BH 20480
#define ST_BL 40960
#define STG   61440
#define SMEMB (2*STG)   // 122880

// ---------------- bf16x3 tensor-core GEMM (R9-proven, term-reordered) -------
template<int QKV>
__global__ void __launch_bounds__(256, 1) gemm_mma(
    const float* __restrict__ Ain,
    const float* __restrict__ W0, const float* __restrict__ W1,
    const float* __restrict__ W2,
    float* __restrict__ Cout)
{
    extern __shared__ __align__(128) char smem[];
    const uint32_t sb = smem_u32(smem);
    const int tid  = threadIdx.x;
    const int lane = tid & 31;
    const int wid  = tid >> 5;

    const float* W; float* dst;
    if (QKV) {
        const int z = blockIdx.y;
        W   = (z == 0) ? W0  : (z == 1) ? W1  : W2;
        dst = (z == 0) ? g_q : (z == 1) ? g_k : g_v;
    } else { W = W0; dst = Cout; }
    const float* Ab = QKV ? Ain : (const float*)g_ao;
    const int m0 = blockIdx.x * 128;

    const int ar = tid & 127;
    const int ah = (tid >> 7) << 4;
    const float* gA = Ab + (size_t)(m0 + ar) * DMOD + ah;
    const uint32_t aDst = (uint32_t)ar * ROWB + (uint32_t)(ah << 1);
    const float* gB = W + tid;
    const uint32_t bDst = (uint32_t)tid * ROWB;

    const int mW = (wid & 1) * 64;
    const int nW = (wid >> 1) * 64;
    const int q  = lane >> 3;
    const int rl = lane & 7;
    const uint32_t aOff = (uint32_t)(mW + (q & 1) * 8 + rl) * ROWB + (uint32_t)((q >> 1) * 16);
    const uint32_t bOff = (uint32_t)(nW + (q >> 1) * 8 + rl) * ROWB + (uint32_t)((q & 1) * 16);

    float acc[4][8][4];
    #pragma unroll
    for (int mi = 0; mi < 4; mi++)
        #pragma unroll
        for (int ni = 0; ni < 8; ni++)
            #pragma unroll
            for (int t = 0; t < 4; t++) acc[mi][ni][t] = 0.f;

    float fa[16], fb[32];

    auto ldgA = [&](int c){
        const float* p = gA + c * 32;
        *(float4*)(fa + 0)  = *(const float4*)(p + 0);
        *(float4*)(fa + 4)  = *(const float4*)(p + 4);
        *(float4*)(fa + 8)  = *(const float4*)(p + 8);
        *(float4*)(fa + 12) = *(const float4*)(p + 12);
    };
    auto ldgB = [&](int c){
        const float* p = gB + (size_t)c * 32 * DMOD;
        #pragma unroll
        for (int i = 0; i < 32; i++) fb[i] = p[(size_t)i * DMOD];
    };
    auto stsAB = [&](uint32_t sBase){
        uint32_t h[16], l[16];
        #pragma unroll
        for (int i = 0; i < 8; i++) bsplit2(fa[2*i], fa[2*i+1], h[i], l[i]);
        sts128(sBase + ST_AH + aDst,      h[0], h[1], h[2], h[3]);
        sts128(sBase + ST_AH + aDst + 16, h[4], h[5], h[6], h[7]);
        sts128(sBase + ST_AL + aDst,      l[0], l[1], l[2], l[3]);
        sts128(sBase + ST_AL + aDst + 16, l[4], l[5], l[6], l[7]);
        #pragma unroll
        for (int i = 0; i < 16; i++) bsplit2(fb[2*i], fb[2*i+1], h[i], l[i]);
        sts128(sBase + ST_BH + bDst,      h[0],  h[1],  h[2],  h[3]);
        sts128(sBase + ST_BH + bDst + 16, h[4],  h[5],  h[6],  h[7]);
        sts128(sBase + ST_BH + bDst + 32, h[8],  h[9],  h[10], h[11]);
        sts128(sBase + ST_BH + bDst + 48, h[12], h[13], h[14], h[15]);
        sts128(sBase + ST_BL + bDst,      l[0],  l[1],  l[2],  l[3]);
        sts128(sBase + ST_BL + bDst + 16, l[4],  l[5],  l[6],  l[7]);
        sts128(sBase + ST_BL + bDst + 32, l[8],  l[9],  l[10], l[11]);
        sts128(sBase + ST_BL + bDst + 48, l[12], l[13], l[14], l[15]);
    };

    ldgA(0); ldgB(0);
    stsAB(sb);
    ldgA(1); ldgB(1);
    __syncthreads();

    #pragma unroll 1
    for (int c = 0; c < 8; c++){
        const uint32_t sBuf = sb + (uint32_t)(c & 1) * STG;
        const uint32_t aH = sBuf + ST_AH + aOff;
        const uint32_t aL = sBuf + ST_AL + aOff;
        const uint32_t bH = sBuf + ST_BH + bOff;
        const uint32_t bL = sBuf + ST_BL + bOff;
        #pragma unroll
        for (int k16 = 0; k16 < 2; k16++){
            const uint32_t ko = (uint32_t)k16 * 32;
            uint32_t A_[16], A2_[16], B_[16];
            #pragma unroll
            for (int mi = 0; mi < 4; mi++)
                ldsm4(A_[4*mi], A_[4*mi+1], A_[4*mi+2], A_[4*mi+3],
                      aH + ko + (uint32_t)mi * (16*ROWB));
            #pragma unroll
            for (int mi = 0; mi < 4; mi++)
                ldsm4(A2_[4*mi], A2_[4*mi+1], A2_[4*mi+2], A2_[4*mi+3],
                      aL + ko + (uint32_t)mi * (16*ROWB));
            #pragma unroll
            for (int j = 0; j < 4; j++)
                ldsm4(B_[4*j], B_[4*j+1], B_[4*j+2], B_[4*j+3],
                      bH + ko + (uint32_t)j * (16*ROWB));
            #pragma unroll
            for (int mi = 0; mi < 4; mi++)
                #pragma unroll
                for (int ni = 0; ni < 8; ni++)
                    mma_bf16(acc[mi][ni], &A_[4*mi], B_[2*ni], B_[2*ni+1]);
            #pragma unroll
            for (int mi = 0; mi < 4; mi++)
                #pragma unroll
                for (int ni = 0; ni < 8; ni++)
                    mma_bf16(acc[mi][ni], &A2_[4*mi], B_[2*ni], B_[2*ni+1]);
            #pragma unroll
            for (int j = 0; j < 4; j++)
                ldsm4(B_[4*j], B_[4*j+1], B_[4*j+2], B_[4*j+3],
                      bL + ko + (uint32_t)j * (16*ROWB));
            #pragma unroll
            for (int mi = 0; mi < 4; mi++)
                #pragma unroll
                for (int ni = 0; ni < 8; ni++)
                    mma_bf16(acc[mi][ni], &A_[4*mi], B_[2*ni], B_[2*ni+1]);
        }
        if (c < 7) stsAB(sb + (uint32_t)((c + 1) & 1) * STG);
        if (c < 6) { ldgA(c + 2); ldgB(c + 2); }
        __syncthreads();
    }

    const int r0q = lane >> 2;
    const int c0q = (lane & 3) * 2;
    #pragma unroll
    for (int mi = 0; mi < 4; mi++){
        #pragma unroll
        for (int half = 0; half < 2; half++){
            const int row = m0 + mW + mi * 16 + half * 8 + r0q;
            if (QKV){
                const int nb = row / SEQ, l = row % SEQ;
                float* base = dst + (((size_t)nb * NHEAD) * SEQ + l) * DHEAD;
                #pragma unroll
                for (int ni = 0; ni < 8; ni++){
                    const int col = nW + ni * 8 + c0q;
                    const int h = col >> 5, cc = col & 31;
                    float2 v;
                    v.x = acc[mi][ni][half*2+0];
                    v.y = acc[mi][ni][half*2+1];
                    *(float2*)(base + (size_t)h * (SEQ*DHEAD) + cc) = v;
                }
            } else {
                float* base = dst + (size_t)row * DMOD;
                #pragma unroll
                for (int ni = 0; ni < 8; ni++){
                    const int col = nW + ni * 8 + c0q;
                    float2 v;
                    v.x = acc[mi][ni][half*2+0];
                    v.y = acc[mi][ni][half*2+1];
                    *(float2*)(base + col) = v;
                }
            }
        }
    }
}

// ---------------- banded attention (R5-proven): one block per (n,h) --------
__global__ void __launch_bounds__(96) attn_kernel(const float* __restrict__ rel_bias)
{
    const int nh = blockIdx.x;
    const int h  = nh & 7;
    const int n  = nh >> 3;

    __shared__ __align__(16) float ks[SEQ][34];
    __shared__ __align__(16) float vs[SEQ][34];
    __shared__ float sbias[NDIAG];

    const int tid = threadIdx.x;
    const float* kg = g_k + (size_t)nh * (SEQ * DHEAD);
    const float* vg = g_v + (size_t)nh * (SEQ * DHEAD);

    for (int idx = tid; idx < SEQ * DHEAD; idx += 96) {
        const int r = idx >> 5, c = idx & 31;
        ks[r][c] = kg[idx];
        vs[r][c] = vg[idx];
    }
    if (tid < NDIAG) {
        const int dd  = tid - 16;
        const int rel = (96 - dd) % 96;
        sbias[tid] = rel_bias[h * 96 + rel];
    }
    __syncthreads();

    const int i = tid;
    const float* qg = g_q + (size_t)nh * (SEQ * DHEAD) + (size_t)i * DHEAD;
    float qv[32];
    #pragma unroll
    for (int c4 = 0; c4 < 8; c4++) {
        float4 t = *(const float4*)(qg + c4 * 4);
        qv[c4*4+0] = t.x; qv[c4*4+1] = t.y; qv[c4*4+2] = t.z; qv[c4*4+3] = t.w;
    }
    ull qq[16];
    #pragma unroll
    for (int t = 0; t < 16; t++) qq[t] = pack2(qv[2*t], qv[2*t+1]);

    const float scale = 0.17677669529663687f;
    float logit[NDIAG];
    #pragma unroll
    for (int d = 0; d < NDIAG; d++) {
        int j = i + d - 16;
        if (j < 0)   j += 96;
        if (j >= 96) j -= 96;
        const ull* kp = (const ull*)&ks[j][0];
        ull a2 = 0ull;
        #pragma unroll
        for (int t = 0; t < 16; t++) ffma2(a2, qq[t], kp[t]);
        float2 s2 = unpack2(a2);
        logit[d] = (s2.x + s2.y) * scale + sbias[d];
    }

    float mx = logit[0];
    #pragma unroll
    for (int d = 1; d < NDIAG; d++) mx = fmaxf(mx, logit[d]);
    float sum = 0.f;
    #pragma unroll
    for (int d = 0; d < NDIAG; d++) { logit[d] = __expf(logit[d] - mx); sum += logit[d]; }

    ull o2[16];
    #pragma unroll
    for (int t = 0; t < 16; t++) o2[t] = 0ull;
    #pragma unroll
    for (int d = 0; d < NDIAG; d++) {
        int j = i + d - 16;
        if (j < 0)   j += 96;
        if (j >= 96) j -= 96;
        const ull ww = pack2(logit[d], logit[d]);
        const ull* vp = (const ull*)&vs[j][0];
        #pragma unroll
        for (int t = 0; t < 16; t++) ffma2(o2[t], ww, vp[t]);
    }

    const float inv = 1.0f / sum;
    float* og = g_ao + ((size_t)n * SEQ + i) * DMOD + h * DHEAD;
    #pragma unroll
    for (int t = 0; t < 16; t++) {
        float2 v = unpack2(o2[t]);
        float2 r; r.x = v.x * inv; r.y = v.y * inv;
        *(float2*)(og + 2 * t) = r;
    }
}

// ---------------- entry point ----------------
extern "C" void kernel_launch(void* const* d_in, const int* in_sizes, int n_in,
                              void* d_out, int out_size)
{
    (void)in_sizes; (void)n_in; (void)out_size;
    const float* Z  = (const float*)d_in[0];
    const float* Wq = (const float*)d_in[1];
    const float* Wk = (const float*)d_in[2];
    const float* Wv = (const float*)d_in[3];
    const float* Wo = (const float*)d_in[4];
    const float* rb = (const float*)d_in[5];
    float* out = (float*)d_out;

    cudaFuncSetAttribute(gemm_mma<1>, cudaFuncAttributeMaxDynamicSharedMemorySize, SMEMB);
    cudaFuncSetAttribute(gemm_mma<0>, cudaFuncAttributeMaxDynamicSharedMemorySize, SMEMB);

    dim3 g1(MTOT / 128, 3);
    gemm_mma<1><<<g1, 256, SMEMB>>>(Z, Wq, Wk, Wv, nullptr);

    attn_kernel<<<NBATCH * NHEAD, 96>>>(rb);

    dim3 g2(MTOT / 128, 1);
    gemm_mma<0><<<g2, 256, SMEMB>>>(nullptr, Wo, nullptr, nullptr, out);
}